// round 17
// baseline (speedup 1.0000x reference)
#include <cuda_runtime.h>
#include <cuda_fp16.h>
#include <math.h>
#include <stdint.h>

// Problem dims
#define BB 32
#define TT 256
#define CC 64
#define HH 64
#define NSM 148

// Output layout (floats)
#define LOGITS_OFF 0
#define DNC_OFF    64
#define MIX_OFF    131136ull              // 64 + 32*4096
#define RL_OFF     33685568ull            // MIX_OFF + 32*256*4096

// ---------------- static device scratch (no runtime allocs) ----------------
__device__ __half g_mx16[8192ull * 4096]; // fp16 mixing copy [b*256+t][4096]
__device__ __half g_w1h[2048ull * 4096];  // clf1_w fp16
__device__ __half g_w2h[1024ull * 2048];  // clf2_w fp16
__device__ __half g_h1h[8192ull * 2048];  // h1 fp16
__device__ float g_lg[512 * 64];          // layer2 fused-clf3 partials
__device__ float g_rl[64];
__device__ int   g_ticket;
__device__ int   g_progress[64];          // per half-CTA, value = t+1
__device__ int   g_rbdone[64];            // [63] = fine-group combined counter
__device__ int   g_pk1done;
__device__ int   g_pk2done;

// ============================================================================
// Base-ISA PTX helpers (sm_80+/sm_90 base — no 'a' features)
// ============================================================================
__device__ __forceinline__ uint32_t smem_u32(const void* p) {
    uint32_t a;
    asm("{ .reg .u64 t; cvta.to.shared.u64 t, %1; cvt.u32.u64 %0, t; }" : "=r"(a) : "l"(p));
    return a;
}
#define CP16(dst, src) \
    asm volatile("cp.async.cg.shared.global [%0], [%1], 16;" :: "r"(dst), "l"(src))
#define CP_COMMIT() asm volatile("cp.async.commit_group;" ::: "memory")
#define CP_WAIT1()  asm volatile("cp.async.wait_group 1;" ::: "memory")
#define CP_WAIT0()  asm volatile("cp.async.wait_group 0;" ::: "memory")
#define LDSM4(R, addr) \
    asm volatile("ldmatrix.sync.aligned.m8n8.x4.shared.b16 {%0,%1,%2,%3}, [%4];" \
        : "=r"((R)[0]), "=r"((R)[1]), "=r"((R)[2]), "=r"((R)[3]) : "r"(addr))
#define LDSM2(R, addr) \
    asm volatile("ldmatrix.sync.aligned.m8n8.x2.shared.b16 {%0,%1}, [%2];" \
        : "=r"((R)[0]), "=r"((R)[1]) : "r"(addr))
#define MMAH(D, A, Bf) \
    asm volatile("mma.sync.aligned.m16n8k16.row.col.f32.f16.f16.f32 " \
        "{%0,%1,%2,%3}, {%4,%5,%6,%7}, {%8,%9}, {%0,%1,%2,%3};" \
        : "+f"((D)[0]), "+f"((D)[1]), "+f"((D)[2]), "+f"((D)[3]) \
        : "r"((A)[0]), "r"((A)[1]), "r"((A)[2]), "r"((A)[3]), "r"((Bf)[0]), "r"((Bf)[1]))

// cluster primitives (sm_90 base ISA)
#define CARRIVE() asm volatile("barrier.cluster.arrive.aligned;" ::: "memory")
#define CWAIT()   asm volatile("barrier.cluster.wait.aligned;" ::: "memory")
__device__ __forceinline__ uint32_t mapa_peer(uint32_t laddr, uint32_t rank) {
    uint32_t r;
    asm("mapa.shared::cluster.u32 %0, %1, %2;" : "=r"(r) : "r"(laddr), "r"(rank));
    return r;
}
#define STC64(addr, v) \
    asm volatile("st.shared::cluster.b64 [%0], %1;" :: "r"(addr), "l"(v) : "memory")
#define STC32(addr, v) \
    asm volatile("st.shared::cluster.b32 [%0], %1;" :: "r"(addr), "r"(v) : "memory")
__device__ __forceinline__ unsigned long long packf2(float a, float b) {
    return ((unsigned long long)__float_as_uint(b) << 32) | __float_as_uint(a);
}

// ---------------- shared mem layout (floats) --------------------------------
#define OFF_WHHT 0          /* [64][192] */
#define OFF_QWT  12288      /* [64][64]  */
#define OFF_KWT  16384      /* [64][64]  */
#define OFF_HT   20480      /* [64 j][34 c-own]  h transposed */
#define OFF_HNT  22656      /* [64 h][34 c-own]  hn transposed */
#define OFF_QROW 24832      /* [32 c][68 a] */
#define OFF_KROW 27008      /* [64 d][68 a]  full (own local + peer DSMEM) */
#define OFF_HNF  31360      /* [64 d][68 j]  full hn */
#define OFF_TRR  37888      /* [32 c][68 d]  gated transfer rows */
#define OFF_XT   40064      /* [2][32] */
#define OFF_A    40128      /* [192] */
#define OFF_B0   40320
#define OFF_BHH  40512
#define OFF_QB   40704
#define OFF_KB   40768
#define OFF_PW   40832
#define OFF_RED  40896      /* [16]; [9] = peer ssq slot */
#define SMEM_FLOATS 40960
#define SMEM_BYTES  (SMEM_FLOATS * 4)

// worker smem carve: bytes [0,32768) A/B bufs; floats: sred s[8192..), tk s[8500]
#define W_SRED 8192
#define W_TK   8500

// ticket queue: 24 packs + L1 reg(tg0..62) 1008 + L1 fine 32 + L2 reg(tg0..63) 512
#define NPK  24
#define NQ   1552
#define NTOT (NPK + NQ)

__device__ __forceinline__ float sigf(float x) { return 1.f / (1.f + __expf(-x)); }
__device__ __forceinline__ float tanh_fast(float x) {
    float e = __expf(2.f * x);
    return __fdividef(e - 1.f, e + 1.f);
}

// ============================================================================
__global__ void init_kernel() {
    int tid = threadIdx.x;
    if (tid == 0) { g_ticket = 0; g_pk1done = 0; g_pk2done = 0; }
    if (tid < 64) {
        g_progress[tid] = 0;
        g_rbdone[tid] = 0;
    }
}

// ============================================================================
// fp16 mma.sync GEMM tile. MI=4: M=128 rowgroup (4-step tg). MI=2: M=64 fine
// rowgroup (2-step, t = 252+2*tg + (r&1)).
// ============================================================================
template <int MI>
__device__ void gemm16(float* s, const __half* __restrict__ Ah,
                       const __half* __restrict__ Bh,
                       const float* __restrict__ bias, int K,
                       int tg, int nb, int layer,
                       const float* __restrict__ w3, int t2)
{
    const int tid = threadIdx.x, lane = tid & 31, wid = tid >> 5;
    const int wm = wid & 1, wn = wid >> 1;
    const int n_blk = nb * 128;
    const uint32_t sAb = smem_u32(s);
    const uint32_t sBb = sAb + 16384;

    const int lr = tid >> 1, lc = (tid & 1) * 2;
    const uint32_t swl = (lr >> 1) & 3;
    const uint32_t dA0 = sAb + lr * 64 + (((uint32_t)lc ^ swl) << 4);
    const uint32_t dA1 = sAb + lr * 64 + (((uint32_t)(lc + 1) ^ swl) << 4);
    const uint32_t dB0 = sBb + lr * 64 + (((uint32_t)lc ^ swl) << 4);
    const uint32_t dB1 = sBb + lr * 64 + (((uint32_t)(lc + 1) ^ swl) << 4);
    const int rowa = (MI == 4) ? ((lr >> 2) * 256 + tg * 4 + (lr & 3))
                               : ((lr >> 1) * 256 + 252 + 2 * tg + (lr & 1));
    const long gA0 = (long)rowa * K + lc * 8;
    const long gB0 = (long)(n_blk + lr) * K + lc * 8;
    const bool doA = (MI == 4) || (lr < 64);

    int rowA[MI], swA[MI], rowB[4], swB[4];
    const int halfA = (lane >> 4) & 1, halfB = (lane >> 3) & 1;
    #pragma unroll
    for (int mi = 0; mi < MI; mi++) {
        rowA[mi] = wm * (16 * MI) + mi * 16 + (lane & 15);
        swA[mi] = (rowA[mi] >> 1) & 3;
    }
    #pragma unroll
    for (int ni = 0; ni < 4; ni++) {
        rowB[ni] = wn * 32 + ni * 8 + (lane & 7);
        swB[ni] = (rowB[ni] >> 1) & 3;
    }

    float acc[MI][4][4];
    #pragma unroll
    for (int mi = 0; mi < MI; mi++)
        #pragma unroll
        for (int ni = 0; ni < 4; ni++)
            #pragma unroll
            for (int r = 0; r < 4; r++) acc[mi][ni][r] = 0.f;

    const int iters = K / 32;
    {
        if (doA) {
            CP16(dA0, Ah + gA0);
            CP16(dA1, Ah + gA0 + 8);
        }
        CP16(dB0, Bh + gB0);
        CP16(dB1, Bh + gB0 + 8);
        CP_COMMIT();
    }
    for (int it = 0; it < iters; ++it) {
        if (it + 1 < iters) {
            uint32_t bo = (uint32_t)((it + 1) & 1) * 8192;
            long ko = (long)(it + 1) * 32;
            if (doA) {
                CP16(dA0 + bo, Ah + gA0 + ko);
                CP16(dA1 + bo, Ah + gA0 + ko + 8);
            }
            CP16(dB0 + bo, Bh + gB0 + ko);
            CP16(dB1 + bo, Bh + gB0 + ko + 8);
            CP_COMMIT();
            CP_WAIT1();
        } else {
            CP_WAIT0();
        }
        __syncthreads();

        uint32_t bo = (uint32_t)(it & 1) * 8192;
        #pragma unroll
        for (int ks = 0; ks < 2; ks++) {
            uint32_t a[MI][4], bfr[4][2];
            #pragma unroll
            for (int mi = 0; mi < MI; mi++)
                LDSM4(a[mi], sAb + bo + rowA[mi] * 64 +
                             (((uint32_t)(2 * ks + halfA) ^ (uint32_t)swA[mi]) << 4));
            #pragma unroll
            for (int ni = 0; ni < 4; ni++)
                LDSM2(bfr[ni], sBb + bo + rowB[ni] * 64 +
                               (((uint32_t)(2 * ks + halfB) ^ (uint32_t)swB[ni]) << 4));
            #pragma unroll
            for (int mi = 0; mi < MI; mi++)
                #pragma unroll
                for (int ni = 0; ni < 4; ni++)
                    MMAH(acc[mi][ni], a[mi], bfr[ni]);
        }
        __syncthreads();
    }

    if (layer == 1) {
        #pragma unroll
        for (int mi = 0; mi < MI; mi++) {
            #pragma unroll
            for (int ni = 0; ni < 4; ni++) {
                int n0 = n_blk + wn * 32 + ni * 8 + (lane & 3) * 2;
                float bs0 = bias[n0], bs1 = bias[n0 + 1];
                #pragma unroll
                for (int h = 0; h < 2; h++) {
                    int ml = wm * (16 * MI) + mi * 16 + (lane >> 2) + h * 8;
                    int row = (MI == 4) ? ((ml >> 2) * 256 + tg * 4 + (ml & 3))
                                        : ((ml >> 1) * 256 + 252 + 2 * tg + (ml & 1));
                    float v0 = fmaxf(acc[mi][ni][h * 2 + 0] + bs0, 0.f);
                    float v1 = fmaxf(acc[mi][ni][h * 2 + 1] + bs1, 0.f);
                    *(__half2*)(g_h1h + (long)row * 2048 + n0) =
                        __floats2half2_rn(v0, v1);
                }
            }
        }
    } else if (MI == 4) {
        float pa[4][2][2];
        #pragma unroll
        for (int mi = 0; mi < 4; mi++)
            #pragma unroll
            for (int h = 0; h < 2; h++) { pa[mi][h][0] = 0.f; pa[mi][h][1] = 0.f; }
        #pragma unroll
        for (int ni = 0; ni < 4; ni++) {
            int n0 = n_blk + wn * 32 + ni * 8 + (lane & 3) * 2;
            float bs0 = bias[n0], bs1 = bias[n0 + 1];
            float wa0 = w3[n0], wa1 = w3[n0 + 1];
            float wb0 = w3[1024 + n0], wb1 = w3[1024 + n0 + 1];
            #pragma unroll
            for (int mi = 0; mi < 4; mi++) {
                #pragma unroll
                for (int h = 0; h < 2; h++) {
                    float v0 = fmaxf(acc[mi][ni][h * 2 + 0] + bs0, 0.f);
                    float v1 = fmaxf(acc[mi][ni][h * 2 + 1] + bs1, 0.f);
                    pa[mi][h][0] = fmaf(v0, wa0, fmaf(v1, wa1, pa[mi][h][0]));
                    pa[mi][h][1] = fmaf(v0, wb0, fmaf(v1, wb1, pa[mi][h][1]));
                }
            }
        }
        #pragma unroll
        for (int mi = 0; mi < 4; mi++)
            #pragma unroll
            for (int h = 0; h < 2; h++)
                #pragma unroll
                for (int o = 0; o < 2; o++) {
                    float v = pa[mi][h][o];
                    #pragma unroll
                    for (int msk = 8; msk > 0; msk >>= 1)
                        v += __shfl_xor_sync(0xffffffffu, v, msk);
                    pa[mi][h][o] = v;
                }
        float* sred = s + W_SRED;
        if ((lane & 15) == 0) {
            #pragma unroll
            for (int mi = 0; mi < 4; mi++)
                #pragma unroll
                for (int h = 0; h < 2; h++) {
                    int bat = wm * 16 + mi * 4 + 2 * h + (lane >> 4);
                    sred[(wn * 32 + bat) * 2 + 0] = pa[mi][h][0];
                    sred[(wn * 32 + bat) * 2 + 1] = pa[mi][h][1];
                }
        }
        __syncthreads();
        if (tid < 64) {
            int b = tid >> 1, o = tid & 1;
            float sv = sred[(0 * 32 + b) * 2 + o] + sred[(1 * 32 + b) * 2 + o]
                     + sred[(2 * 32 + b) * 2 + o] + sred[(3 * 32 + b) * 2 + o];
            g_lg[t2 * 64 + b * 2 + o] = sv;
        }
        __syncthreads();
    }
}

// ============================================================================
// Mega kernel: blocks 0..63 = cluster-paired split recurrence, then workers
// ============================================================================
__global__ __launch_bounds__(256) void mega_kernel(
    const float* __restrict__ x,
    const float* __restrict__ emb_w, const float* __restrict__ emb_b,
    const float* __restrict__ w_ih, const float* __restrict__ w_hh,
    const float* __restrict__ b_ih, const float* __restrict__ b_hh,
    const float* __restrict__ q_w, const float* __restrict__ q_b,
    const float* __restrict__ k_w, const float* __restrict__ k_b,
    const float* __restrict__ gate_b,
    const float* __restrict__ pred_w, const float* __restrict__ pred_b,
    const float* __restrict__ clf1_w, const float* __restrict__ clf1_b,
    const float* __restrict__ clf2_w, const float* __restrict__ clf2_b,
    const float* __restrict__ clf3_w,
    float* __restrict__ out)
{
    extern __shared__ float s[];
    const int tid = threadIdx.x;
    const int bidx = blockIdx.x;

    if (bidx < 64) {
        const int b = bidx >> 1, half = bidx & 1;
        const int ph = half ^ 1;
        const uint32_t prank = (uint32_t)ph;
        const int tx = tid & 15, ty = tid >> 4;
        const int j0 = 4 * tx;
        const uint32_t sbase = smem_u32(s);

        // ---- weight loads ----
        for (int i = tid; i < 12288; i += 256) {
            int j = i / 64, h = i % 64;
            s[OFF_WHHT + h * 192 + j] = w_hh[i];
        }
        for (int i = tid; i < 4096; i += 256) {
            int j = i / 64, h = i % 64;
            s[OFF_QWT + h * 64 + j] = q_w[i];
            s[OFF_KWT + h * 64 + j] = k_w[i];
        }
        if (tid < 192) {
            float a = 0.f, b0v = 0.f;
            #pragma unroll
            for (int e = 0; e < 32; e++) {
                float w = w_ih[tid * 32 + e];
                a += w * emb_w[e];
                b0v += w * emb_b[e];
            }
            s[OFF_A + tid] = a;
            s[OFF_B0 + tid] = b0v + b_ih[tid];
            s[OFF_BHH + tid] = b_hh[tid];
        }
        if (tid < 64) {
            s[OFF_QB + tid] = q_b[tid];
            s[OFF_KB + tid] = k_b[tid];
            s[OFF_PW + tid] = pred_w[tid];
        }
        if (tid < 32)
            s[OFF_XT + tid] = x[(size_t)b * TT * CC + half * 32 + tid];
        for (int i = tid; i < 64 * 34; i += 256) s[OFF_HT + i] = 0.f;
        const float pb = pred_b[0];
        float errsum = 0.f;
        __syncthreads();

        float Ar[4], Az[4], An[4], B0r[4], B0z[4], B0n[4];
        float Br[4], Bz[4], Bn[4], QBv[4], KBv[4];
        #pragma unroll
        for (int ji = 0; ji < 4; ji++) {
            int j = j0 + ji;
            Ar[ji] = s[OFF_A + j];  Az[ji] = s[OFF_A + 64 + j];  An[ji] = s[OFF_A + 128 + j];
            B0r[ji] = s[OFF_B0 + j]; B0z[ji] = s[OFF_B0 + 64 + j]; B0n[ji] = s[OFF_B0 + 128 + j];
            Br[ji] = s[OFF_BHH + j]; Bz[ji] = s[OFF_BHH + 64 + j]; Bn[ji] = s[OFF_BHH + 128 + j];
            QBv[ji] = s[OFF_QB + j]; KBv[ji] = s[OFF_KB + j];
        }
        float GT[8], DNCr[8];
        #pragma unroll
        for (int hd = 0; hd < 2; hd++) {
            int dsel = hd ? ph : half;
            #pragma unroll
            for (int cc = 0; cc < 2; cc++)
                #pragma unroll
                for (int dd = 0; dd < 2; dd++) {
                    GT[hd*4 + cc*2 + dd] =
                        gate_b[(half*32 + 2*tx + cc) * 64 + dsel*32 + 2*ty + dd];
                    DNCr[hd*4 + cc*2 + dd] = 0.f;
                }
        }

        uint32_t pHNF[2], pKROW[2];
        #pragma unroll
        for (int cc = 0; cc < 2; cc++) {
            pHNF[cc]  = mapa_peer(sbase + (uint32_t)(OFF_HNF  + (half*32 + 2*ty + cc) * 68 + j0) * 4, prank);
            pKROW[cc] = mapa_peer(sbase + (uint32_t)(OFF_KROW + (half*32 + 2*ty + cc) * 68 + j0) * 4, prank);
        }
        const uint32_t pSSQ = mapa_peer(sbase + (uint32_t)(OFF_RED + 9) * 4, prank);

        CARRIVE();   // prime barrier generation for first wait (#a)

        for (int t = 0; t < TT; t++) {
            const int par = t & 1;
            // ---- Phase 1: gh = h @ w_hh^T ----
            float ar[8], az[8], an_[8];
            #pragma unroll
            for (int ji = 0; ji < 4; ji++) {
                ar[ji] = Br[ji];  ar[4 + ji] = Br[ji];
                az[ji] = Bz[ji];  az[4 + ji] = Bz[ji];
                an_[ji] = Bn[ji]; an_[4 + ji] = Bn[ji];
            }
            #pragma unroll 4
            for (int h = 0; h < 64; h++) {
                float2 hv2 = *(const float2*)&s[OFF_HT + h * 34 + 2 * ty];
                float4 wr4 = *(const float4*)&s[OFF_WHHT + h * 192 + j0];
                float4 wz4 = *(const float4*)&s[OFF_WHHT + h * 192 + 64 + j0];
                float4 wn4 = *(const float4*)&s[OFF_WHHT + h * 192 + 128 + j0];
                float wr[4] = {wr4.x, wr4.y, wr4.z, wr4.w};
                float wz[4] = {wz4.x, wz4.y, wz4.z, wz4.w};
                float wn[4] = {wn4.x, wn4.y, wn4.z, wn4.w};
                #pragma unroll
                for (int ji = 0; ji < 4; ji++) {
                    ar[ji]  = fmaf(hv2.x, wr[ji], ar[ji]);
                    az[ji]  = fmaf(hv2.x, wz[ji], az[ji]);
                    an_[ji] = fmaf(hv2.x, wn[ji], an_[ji]);
                    ar[4+ji]  = fmaf(hv2.y, wr[ji], ar[4+ji]);
                    az[4+ji]  = fmaf(hv2.y, wz[ji], az[4+ji]);
                    an_[4+ji] = fmaf(hv2.y, wn[ji], an_[4+ji]);
                }
            }

            CWAIT();   // #a: safe to overwrite peer HNF/KROW

            // ---- Phase 2: gates -> hn; publish ----
            float hnreg[8];
            float xv0 = s[OFF_XT + par * 32 + 2 * ty];
            float xv1 = s[OFF_XT + par * 32 + 2 * ty + 1];
            #pragma unroll
            for (int ji = 0; ji < 4; ji++) {
                float2 ho = *(const float2*)&s[OFF_HT + (j0 + ji) * 34 + 2 * ty];
                {
                    float gir = fmaf(xv0, Ar[ji], B0r[ji]);
                    float giz = fmaf(xv0, Az[ji], B0z[ji]);
                    float gin = fmaf(xv0, An[ji], B0n[ji]);
                    float r = sigf(gir + ar[ji]);
                    float z = sigf(giz + az[ji]);
                    float n = tanh_fast(fmaf(r, an_[ji], gin));
                    hnreg[ji] = (1.f - z) * n + z * ho.x;
                }
                {
                    float gir = fmaf(xv1, Ar[ji], B0r[ji]);
                    float giz = fmaf(xv1, Az[ji], B0z[ji]);
                    float gin = fmaf(xv1, An[ji], B0n[ji]);
                    float r = sigf(gir + ar[4+ji]);
                    float z = sigf(giz + az[4+ji]);
                    float n = tanh_fast(fmaf(r, an_[4+ji], gin));
                    hnreg[4 + ji] = (1.f - z) * n + z * ho.y;
                }
                float2 w2; w2.x = hnreg[ji]; w2.y = hnreg[4 + ji];
                *(float2*)&s[OFF_HNT + (j0 + ji) * 34 + 2 * ty] = w2;
            }
            #pragma unroll
            for (int cc = 0; cc < 2; cc++) {
                float4 v; v.x = hnreg[cc*4+0]; v.y = hnreg[cc*4+1];
                v.z = hnreg[cc*4+2]; v.w = hnreg[cc*4+3];
                *(float4*)&s[OFF_HNF + (half*32 + 2*ty + cc) * 68 + j0] = v;
                STC64(pHNF[cc],     packf2(v.x, v.y));
                STC64(pHNF[cc] + 8, packf2(v.z, v.w));
            }
            __syncthreads();

            // ---- Phase 3: q/k; publish own k half ----
            float aq[8], ak[8];
            #pragma unroll
            for (int ji = 0; ji < 4; ji++) {
                aq[ji] = QBv[ji]; aq[4+ji] = QBv[ji];
                ak[ji] = KBv[ji]; ak[4+ji] = KBv[ji];
            }
            #pragma unroll 4
            for (int h = 0; h < 64; h++) {
                float2 hv2 = *(const float2*)&s[OFF_HNT + h * 34 + 2 * ty];
                float4 qw4 = *(const float4*)&s[OFF_QWT + h * 64 + j0];
                float4 kw4 = *(const float4*)&s[OFF_KWT + h * 64 + j0];
                float qw[4] = {qw4.x, qw4.y, qw4.z, qw4.w};
                float kw[4] = {kw4.x, kw4.y, kw4.z, kw4.w};
                #pragma unroll
                for (int ji = 0; ji < 4; ji++) {
                    aq[ji]   = fmaf(hv2.x, qw[ji], aq[ji]);
                    ak[ji]   = fmaf(hv2.x, kw[ji], ak[ji]);
                    aq[4+ji] = fmaf(hv2.y, qw[ji], aq[4+ji]);
                    ak[4+ji] = fmaf(hv2.y, kw[ji], ak[4+ji]);
                }
            }
            #pragma unroll
            for (int cc = 0; cc < 2; cc++) {
                float4 qv; qv.x = aq[cc*4+0]; qv.y = aq[cc*4+1];
                qv.z = aq[cc*4+2]; qv.w = aq[cc*4+3];
                float4 kv; kv.x = ak[cc*4+0]; kv.y = ak[cc*4+1];
                kv.z = ak[cc*4+2]; kv.w = ak[cc*4+3];
                *(float4*)&s[OFF_QROW + (2*ty + cc) * 68 + j0] = qv;
                *(float4*)&s[OFF_KROW + (half*32 + 2*ty + cc) * 68 + j0] = kv;
                STC64(pKROW[cc],     packf2(kv.x, kv.y));
                STC64(pKROW[cc] + 8, packf2(kv.z, kv.w));
            }
            __syncthreads();
            CARRIVE();   // #b

            // ---- Phase 4a: tr own-d half ----
            float tr[8];
            #pragma unroll
            for (int i = 0; i < 8; i++) tr[i] = 0.f;
            {
                int drow = half * 32 + 2 * ty;
                #pragma unroll 2
                for (int a4 = 0; a4 < 64; a4 += 4) {
                    float4 q0 = *(const float4*)&s[OFF_QROW + (2*tx) * 68 + a4];
                    float4 q1 = *(const float4*)&s[OFF_QROW + (2*tx + 1) * 68 + a4];
                    float4 k0 = *(const float4*)&s[OFF_KROW + drow * 68 + a4];
                    float4 k1 = *(const float4*)&s[OFF_KROW + (drow + 1) * 68 + a4];
                    const float* qa0 = &q0.x; const float* qa1 = &q1.x;
                    const float* ka0 = &k0.x; const float* ka1 = &k1.x;
                    #pragma unroll
                    for (int ai = 0; ai < 4; ai++) {
                        tr[0] = fmaf(qa0[ai], ka0[ai], tr[0]);
                        tr[1] = fmaf(qa0[ai], ka1[ai], tr[1]);
                        tr[2] = fmaf(qa1[ai], ka0[ai], tr[2]);
                        tr[3] = fmaf(qa1[ai], ka1[ai], tr[3]);
                    }
                }
            }
            CWAIT();     // #b acquire

            // ---- Phase 4b: tr peer-d half ----
            {
                int drow = ph * 32 + 2 * ty;
                #pragma unroll 2
                for (int a4 = 0; a4 < 64; a4 += 4) {
                    float4 q0 = *(const float4*)&s[OFF_QROW + (2*tx) * 68 + a4];
                    float4 q1 = *(const float4*)&s[OFF_QROW + (2*tx + 1) * 68 + a4];
                    float4 k0 = *(const float4*)&s[OFF_KROW + drow * 68 + a4];
                    float4 k1 = *(const float4*)&s[OFF_KROW + (drow + 1) * 68 + a4];
                    const float* qa0 = &q0.x; const float* qa1 = &q1.x;
                    const float* ka0 = &k0.x; const float* ka1 = &k1.x;
                    #pragma unroll
                    for (int ai = 0; ai < 4; ai++) {
                        tr[4] = fmaf(qa0[ai], ka0[ai], tr[4]);
                        tr[5] = fmaf(qa0[ai], ka1[ai], tr[5]);
                        tr[6] = fmaf(qa1[ai], ka0[ai], tr[6]);
                        tr[7] = fmaf(qa1[ai], ka1[ai], tr[7]);
                    }
                }
            }

            // ---- Frobenius norm exchange ----
            float ssq = 0.f;
            #pragma unroll
            for (int i = 0; i < 8; i++) ssq = fmaf(tr[i], tr[i], ssq);
            #pragma unroll
            for (int o = 16; o > 0; o >>= 1) ssq += __shfl_xor_sync(0xffffffffu, ssq, o);
            if ((tid & 31) == 0) s[OFF_RED + (tid >> 5)] = ssq;
            __syncthreads();
            float ownTot = 0.f;
            #pragma unroll
            for (int w = 0; w < 8; w++) ownTot += s[OFF_RED + w];
            if (tid == 0) STC32(pSSQ, __float_as_uint(ownTot));
            CARRIVE();   // #c
            // hide part of #c wait behind the x[t+1] prefetch
            if (tid < 32 && t + 1 < TT)
                s[OFF_XT + ((t + 1) & 1) * 32 + tid] =
                    x[((size_t)b * TT + t + 1) * CC + half * 32 + tid];
            CWAIT();
            float rn = rsqrtf(ownTot + s[OFF_RED + 9]);

            // ---- gates -> gated transfer rows ----
            float tt[8];
            #pragma unroll
            for (int hd = 0; hd < 2; hd++) {
                int dsel = hd ? ph : half;
                #pragma unroll
                for (int cc = 0; cc < 2; cc++) {
                    #pragma unroll
                    for (int dd = 0; dd < 2; dd++) {
                        int i = hd*4 + cc*2 + dd;
                        float tv = tanh_fast(tr[i] * rn);
                        float g = sigf(fabsf(tv) + GT[i]);
                        tv *= g;
                        tt[i] = tv;
                        DNCr[i] += tv;
                    }
                    float2 w2; w2.x = tt[hd*4 + cc*2]; w2.y = tt[hd*4 + cc*2 + 1];
                    *(float2*)&s[OFF_TRR + (2*tx + cc) * 68 + dsel*32 + 2*ty] = w2;
                }
            }
            __syncthreads();

            {   // coalesced mixing + fp16 copy (bounce via TRR)
                int r = tid >> 3, c8 = (tid & 7) * 8;
                float4 m0 = *(const float4*)&s[OFF_TRR + r * 68 + c8];
                float4 m1 = *(const float4*)&s[OFF_TRR + r * 68 + c8 + 4];
                size_t rowb = ((size_t)(b * TT + t)) * 4096 + (half*32 + r) * 64 + c8;
                *(float4*)&out[MIX_OFF + rowb] = m0;
                *(float4*)&out[MIX_OFF + rowb + 4] = m1;
                __half2 a0 = __floats2half2_rn(m0.x, m0.y);
                __half2 a1 = __floats2half2_rn(m0.z, m0.w);
                __half2 a2 = __floats2half2_rn(m1.x, m1.y);
                __half2 a3 = __floats2half2_rn(m1.z, m1.w);
                uint4 pk;
                pk.x = *(uint32_t*)&a0; pk.y = *(uint32_t*)&a1;
                pk.z = *(uint32_t*)&a2; pk.w = *(uint32_t*)&a3;
                *(uint4*)(g_mx16 + rowb) = pk;
            }
            // (no sync needed: phase5 reads TRR/HNF, both already synced)

            // ---- Phase 5: h_next = tr @ hn ----
            float ah[8];
            #pragma unroll
            for (int i = 0; i < 8; i++) ah[i] = 0.f;
            #pragma unroll 2
            for (int d4 = 0; d4 < 64; d4 += 4) {
                float4 t0 = *(const float4*)&s[OFF_TRR + (2*tx) * 68 + d4];
                float4 t1 = *(const float4*)&s[OFF_TRR + (2*tx + 1) * 68 + d4];
                const float* ta = &t0.x; const float* tb = &t1.x;
                #pragma unroll
                for (int i = 0; i < 4; i++) {
                    float4 hv4 = *(const float4*)&s[OFF_HNF + (d4 + i) * 68 + 4 * ty];
                    const float* hv = &hv4.x;
                    #pragma unroll
                    for (int ji = 0; ji < 4; ji++) {
                        ah[ji]   = fmaf(ta[i], hv[ji], ah[ji]);
                        ah[4+ji] = fmaf(tb[i], hv[ji], ah[4+ji]);
                    }
                }
            }
            #pragma unroll
            for (int ji = 0; ji < 4; ji++) {
                float2 w2; w2.x = ah[ji]; w2.y = ah[4 + ji];
                *(float2*)&s[OFF_HT + (4*ty + ji) * 34 + 2 * tx] = w2;
            }
            CARRIVE();   // #a for next step
            __syncthreads();
            if (tid == 0) { __threadfence(); atomicExch(&g_progress[bidx], t + 1); }

            if (tid < 32 && t >= 1) {
                float p = pb;
                #pragma unroll 8
                for (int h = 0; h < 64; h++)
                    p = fmaf(s[OFF_HT + h * 34 + tid], s[OFF_PW + h], p);
                float dd = p - s[OFF_XT + par * 32 + tid];
                errsum = fmaf(dd, dd, errsum);
            }
        }
        CWAIT();   // retire final generation

        #pragma unroll
        for (int hd = 0; hd < 2; hd++) {
            int dsel = hd ? ph : half;
            #pragma unroll
            for (int cc = 0; cc < 2; cc++) {
                float2 v;
                v.x = DNCr[hd*4 + cc*2 + 0] * (1.f / 256.f);
                v.y = DNCr[hd*4 + cc*2 + 1] * (1.f / 256.f);
                *(float2*)&out[DNC_OFF + (size_t)b * 4096 +
                               (size_t)(half*32 + 2*tx + cc) * 64 + dsel*32 + 2*ty] = v;
            }
        }
        if (tid < 32) {
            #pragma unroll
            for (int o = 16; o > 0; o >>= 1)
                errsum += __shfl_xor_sync(0xffffffffu, errsum, o);
            if (tid == 0) g_rl[bidx] = errsum;
        }
        __syncthreads();   // fall through to worker role
    }

    // ------------------------------------------------------------------
    // Role 2: worker (all blocks)
    // ------------------------------------------------------------------
    int* stk = (int*)&s[W_TK];
    for (;;) {
        __syncthreads();
        if (tid == 0) stk[0] = atomicAdd(&g_ticket, 1);
        __syncthreads();
        int tk = stk[0];
        if (tk >= NTOT) break;

        if (tk < NPK) {
            if (tk < 16) {
                long base = (long)tk * 524288;
                const float2* src = (const float2*)(clf1_w + base);
                __half2* dst = (__half2*)(g_w1h + base);
                for (int i = tid; i < 262144; i += 256) {
                    float2 v = src[i];
                    dst[i] = __floats2half2_rn(v.x, v.y);
                }
                __threadfence();
                __syncthreads();
                if (tid == 0) atomicAdd(&g_pk1done, 1);
            } else {
                long base = (long)(tk - 16) * 262144;
                const float2* src = (const float2*)(clf2_w + base);
                __half2* dst = (__half2*)(g_w2h + base);
                for (int i = tid; i < 131072; i += 256) {
                    float2 v = src[i];
                    dst[i] = __floats2half2_rn(v.x, v.y);
                }
                __threadfence();
                __syncthreads();
                if (tid == 0) atomicAdd(&g_pk2done, 1);
            }
            continue;
        }

        // decode: L1 reg (ly=1, tg 0..62), L2 reg (ly=2, tg 0..63), L1 fine (ly=3, fg 0..1)
        int u = tk - NPK;
        int ly, tg, nb;
        if (u < 16) { ly = 1; tg = 0; nb = u; }
        else if (u < 1504) {
            int v = u - 16, g = v / 24, r = v - g * 24;
            if (r < 8) { ly = 2; tg = g; nb = r; }
            else       { ly = 1; tg = g + 1; nb = r - 8; }
        } else {
            int u2 = u - 1504;
            if (u2 < 8)       { ly = 2; tg = 62; nb = u2; }
            else if (u2 < 24) { ly = 3; tg = 0;  nb = u2 - 8; }
            else if (u2 < 40) { ly = 3; tg = 1;  nb = u2 - 24; }
            else              { ly = 2; tg = 63; nb = u2 - 40; }
        }

        if (ly == 1 || ly == 3) {
            if (tid == 0) {
                volatile int* pk = &g_pk1done;
                while (*pk < 16) __nanosleep(128);
                int need = (ly == 1) ? (tg + 1) * 4 : (254 + 2 * tg);
                for (int bi = 0; bi < 64; bi++) {
                    volatile int* p = &g_progress[bi];
                    while (*p < need) __nanosleep(128);
                }
                __threadfence();
            }
            __syncthreads();
            if (ly == 1)
                gemm16<4>(s, g_mx16, g_w1h, clf1_b, 4096, tg, nb, 1, nullptr, 0);
            else
                gemm16<2>(s, g_mx16, g_w1h, clf1_b, 4096, tg, nb, 1, nullptr, 0);
            __threadfence();
            __syncthreads();
            if (tid == 0) atomicAdd(&g_rbdone[(ly == 1) ? tg : 63], 1);
        } else {
            if (tid == 0) {
                volatile int* pk = &g_pk2done;
                while (*pk < 8) __nanosleep(128);
                int target = (tg == 63) ? 32 : 16;
                volatile int* rd = &g_rbdone[tg];
                while (*rd < target) __nanosleep(128);
                __threadfence();
            }
            __syncthreads();
            gemm16<4>(s, g_h1h, g_w2h, clf2_b, 2048, tg, nb, 2, clf3_w, tg * 8 + nb);
        }
    }
}

// ============================================================================
__global__ void finalize_kernel(const float* __restrict__ b3, float* __restrict__ out)
{
    int tid = threadIdx.x;
    if (tid < 64) {
        int b = tid >> 1, o = tid & 1;
        float sv = 0.f;
        for (int t2 = 0; t2 < 512; t2++)
            sv += g_lg[t2 * 64 + b * 2 + o];
        out[(size_t)b * 2 + o] = sv * (1.f / 256.f) + b3[o];
    }
    if (tid == 64) {
        float ss = 0.f;
        #pragma unroll
        for (int i = 0; i < 64; i++) ss += g_rl[i];
        out[RL_OFF] = ss / (32.f * 255.f * 64.f);
    }
}

// ============================================================================
extern "C" void kernel_launch(void* const* d_in, const int* in_sizes, int n_in,
                              void* d_out, int out_size)
{
    const float* x      = (const float*)d_in[0];
    const float* emb_w  = (const float*)d_in[1];
    const float* emb_b  = (const float*)d_in[2];
    const float* w_ih   = (const float*)d_in[3];
    const float* w_hh   = (const float*)d_in[4];
    const float* b_ih   = (const float*)d_in[5];
    const float* b_hh   = (const float*)d_in[6];
    const float* q_w    = (const float*)d_in[7];
    const float* q_b    = (const float*)d_in[8];
    const float* k_w    = (const float*)d_in[9];
    const float* k_b    = (const float*)d_in[10];
    const float* gate_b = (const float*)d_in[11];
    const float* pred_w = (const float*)d_in[12];
    const float* pred_b = (const float*)d_in[13];
    const float* clf1_w = (const float*)d_in[14];
    const float* clf1_b = (const float*)d_in[15];
    const float* clf2_w = (const float*)d_in[16];
    const float* clf2_b = (const float*)d_in[17];
    const float* clf3_w = (const float*)d_in[18];
    const float* clf3_b = (const float*)d_in[19];
    float* out = (float*)d_out;

    cudaFuncSetAttribute(mega_kernel,
                         cudaFuncAttributeMaxDynamicSharedMemorySize, SMEM_BYTES);

    init_kernel<<<1, 128>>>();

    cudaLaunchConfig_t cfg = {};
    cfg.gridDim = dim3(NSM, 1, 1);
    cfg.blockDim = dim3(256, 1, 1);
    cfg.dynamicSmemBytes = SMEM_BYTES;
    cfg.stream = 0;
    cudaLaunchAttribute attrs[1];
    attrs[0].id = cudaLaunchAttributeClusterDimension;
    attrs[0].val.clusterDim.x = 2;
    attrs[0].val.clusterDim.y = 1;
    attrs[0].val.clusterDim.z = 1;
    cfg.attrs = attrs;
    cfg.numAttrs = 1;
    cudaLaunchKernelEx(&cfg, mega_kernel,
        x, emb_w, emb_b, w_ih, w_hh, b_ih, b_hh,
        q_w, q_b, k_w, k_b, gate_b, pred_w, pred_b,
        clf1_w, clf1_b, clf2_w, clf2_b, clf3_w, out);

    finalize_kernel<<<1, 128>>>(clf3_b, out);
}